// round 10
// baseline (speedup 1.0000x reference)
#include <cuda_runtime.h>
#include <cstdint>

// ---------------- problem constants ----------------
#define ROWG   64
#define IN_DIM 1024
#define OUT_D  1024
#define BATCH  512

// ---------------- tiling ----------------
#define BM 128
#define BN 256
#define BK 32
#define KT (IN_DIM / BK)   // 32 k-tiles

// ---------------- smem layout (bytes) ----------------
#define A_ROW_B 64                  // 32 fp16, no pad (XOR swizzle)
#define A_STG   (BM * A_ROW_B)      // 8192
#define B_ROW_B 528                 // 256 fp16 (512B) + 16B pad
#define B_STG   (BK * B_ROW_B)      // 16896
#define SMEM_TOTAL (2 * (A_STG + B_STG))  // 50176

__device__ __forceinline__ uint32_t packh(float hi, float lo) {
    uint32_t w;
    asm("cvt.rn.f16x2.f32 %0, %1, %2;" : "=r"(w) : "f"(hi), "f"(lo));
    return w;
}

#define LDSM4(R, ADDR) \
    asm volatile("ldmatrix.sync.aligned.m8n8.x4.shared.b16 {%0,%1,%2,%3}, [%4];" \
        : "=r"((R)[0]), "=r"((R)[1]), "=r"((R)[2]), "=r"((R)[3]) : "r"(ADDR))

#define LDSM4T(R, ADDR) \
    asm volatile("ldmatrix.sync.aligned.m8n8.x4.trans.shared.b16 {%0,%1,%2,%3}, [%4];" \
        : "=r"((R)[0]), "=r"((R)[1]), "=r"((R)[2]), "=r"((R)[3]) : "r"(ADDR))

#define MMA16(C, A, B0, B1) \
    asm volatile("mma.sync.aligned.m16n8k16.row.col.f32.f16.f16.f32 " \
        "{%0,%1,%2,%3}, {%4,%5,%6,%7}, {%8,%9}, {%0,%1,%2,%3};" \
        : "+f"((C)[0]), "+f"((C)[1]), "+f"((C)[2]), "+f"((C)[3]) \
        : "r"((A)[0]), "r"((A)[1]), "r"((A)[2]), "r"((A)[3]), "r"(B0), "r"(B1))

__global__ __launch_bounds__(256, 1)
void gmlp_f16pipe(const float* __restrict__ x,
                  const float* __restrict__ W,
                  const float* __restrict__ bias,
                  float* __restrict__ out)
{
    extern __shared__ __align__(16) char smem[];
    const uint32_t sbA = (uint32_t)__cvta_generic_to_shared(smem);
    const uint32_t sbB = sbA + 2 * A_STG;

    const int r  = blockIdx.z;
    const int n0 = blockIdx.x * BN;
    const int m0 = blockIdx.y * BM;

    const int tid  = threadIdx.x;
    const int wid  = tid >> 5;
    const int lane = tid & 31;
    const int wm   = wid & 1;            // 2 m-warps of 64 rows
    const int wn   = wid >> 1;           // 4 n-warps of 64 cols
    const int g    = lane >> 2;
    const int tg   = lane & 3;

    // ---- loader: A (128 rows x 32 fp32), fully coalesced ----
    const int arow = tid >> 2;
    const int ak   = (tid & 3) * 8;
    const float* xA = x + (size_t)(m0 + arow) * (ROWG * IN_DIM)
                        + (size_t)r * IN_DIM + ak;
    const size_t A_C1 = (size_t)64 * (ROWG * IN_DIM);
    const uint32_t saA = sbA + arow * A_ROW_B
                       + (((tid & 3) ^ ((tid >> 3) & 3)) * 16);

    // ---- loader: B (32 k-rows x 256 fp32), fully coalesced ----
    const int brow = tid >> 3;
    const float* xB = W + (size_t)r * IN_DIM * OUT_D
                        + (size_t)brow * OUT_D + n0 + (tid & 7) * 8;
    const uint32_t saB = sbB + brow * B_ROW_B + (tid & 7) * 16;

    // ---- consumer ldmatrix base addresses ----
    const int v = ((lane & 15) >> 1) & 3;
    const int h = lane >> 4;
    const uint32_t aBase = sbA + (wm * 64 + (lane & 15)) * A_ROW_B + ((h ^ v) * 16);
    const uint32_t bBase = sbB + ((lane & 7) + ((lane >> 3) & 1) * 8) * B_ROW_B
                               + (wn * 8 + h) * 16;

    float acc[4][8][4];
    #pragma unroll
    for (int mt = 0; mt < 4; mt++)
        #pragma unroll
        for (int nt = 0; nt < 8; nt++)
            #pragma unroll
            for (int i = 0; i < 4; i++)
                acc[mt][nt][i] = 0.0f;

    float stA[16], stB[32];

#define LOAD_GLB(T) do {                                                     \
    const float4* a0_ = (const float4*)(xA + (size_t)(T) * BK);              \
    const float4* a1_ = (const float4*)(xA + (size_t)(T) * BK + A_C1);       \
    float4 v_;                                                               \
    v_ = a0_[0]; stA[0]=v_.x; stA[1]=v_.y; stA[2]=v_.z; stA[3]=v_.w;         \
    v_ = a0_[1]; stA[4]=v_.x; stA[5]=v_.y; stA[6]=v_.z; stA[7]=v_.w;         \
    v_ = a1_[0]; stA[8]=v_.x; stA[9]=v_.y; stA[10]=v_.z; stA[11]=v_.w;       \
    v_ = a1_[1]; stA[12]=v_.x; stA[13]=v_.y; stA[14]=v_.z; stA[15]=v_.w;     \
    _Pragma("unroll")                                                        \
    for (int c_ = 0; c_ < 4; c_++) {                                         \
        const float4* b_ = (const float4*)(xB + (size_t)(T) * BK * OUT_D + c_ * 64); \
        float4 u0_ = b_[0], u1_ = b_[1];                                     \
        stB[c_*8+0]=u0_.x; stB[c_*8+1]=u0_.y; stB[c_*8+2]=u0_.z; stB[c_*8+3]=u0_.w; \
        stB[c_*8+4]=u1_.x; stB[c_*8+5]=u1_.y; stB[c_*8+6]=u1_.z; stB[c_*8+7]=u1_.w; \
    }                                                                        \
} while (0)

#define STS_TILE(BUF) do {                                                   \
    asm volatile("st.shared.v4.b32 [%0], {%1,%2,%3,%4};"                     \
        :: "r"(saA + (BUF) * A_STG),                                         \
           "r"(packh(stA[1],stA[0])), "r"(packh(stA[3],stA[2])),             \
           "r"(packh(stA[5],stA[4])), "r"(packh(stA[7],stA[6])));            \
    asm volatile("st.shared.v4.b32 [%0], {%1,%2,%3,%4};"                     \
        :: "r"(saA + (BUF) * A_STG + 64 * A_ROW_B),                          \
           "r"(packh(stA[9],stA[8])), "r"(packh(stA[11],stA[10])),           \
           "r"(packh(stA[13],stA[12])), "r"(packh(stA[15],stA[14])));        \
    _Pragma("unroll")                                                        \
    for (int c_ = 0; c_ < 4; c_++) {                                         \
        asm volatile("st.shared.v4.b32 [%0], {%1,%2,%3,%4};"                 \
            :: "r"(saB + (BUF) * B_STG + c_ * 128),                          \
               "r"(packh(stB[c_*8+1],stB[c_*8+0])), "r"(packh(stB[c_*8+3],stB[c_*8+2])), \
               "r"(packh(stB[c_*8+5],stB[c_*8+4])), "r"(packh(stB[c_*8+7],stB[c_*8+6]))); \
    }                                                                        \
} while (0)

    // ---- prologue ----
    LOAD_GLB(0);
    STS_TILE(0);
    __syncthreads();

    // ---- main loop: 2-buffer ring, software-pipelined fragments ----
    #pragma unroll 1
    for (int kt = 0; kt < KT; kt++) {
        const int buf = kt & 1;
        const uint32_t aT = aBase + buf * A_STG;
        const uint32_t bT = bBase + buf * B_STG;

        if (kt + 1 < KT) LOAD_GLB(kt + 1);

        // fragment pipeline: 8 groups (ks = grp>>2, p = grp&3)
        uint32_t aF[2][4][4];   // [ks][mt][4]
        uint32_t bF[2][4];      // double buffer

        #pragma unroll
        for (int mt = 0; mt < 4; mt++)
            LDSM4(aF[0][mt], (aT + mt * (16 * A_ROW_B)));
        LDSM4T(bF[0], bT);

        #pragma unroll
        for (int grp = 0; grp < 8; grp++) {
            const int ks = grp >> 2;
            const int p  = grp & 3;
            const int nb = grp & 1;
            if (grp < 7) {
                const int g1 = grp + 1;
                LDSM4T(bF[nb ^ 1], bT + (g1 >> 2) * (16 * B_ROW_B) + (g1 & 3) * 32);
            }
            if (grp == 2) {
                #pragma unroll
                for (int mt = 0; mt < 4; mt++)
                    LDSM4(aF[1][mt], (aT + mt * (16 * A_ROW_B)) ^ 32);
            }
            #pragma unroll
            for (int mt = 0; mt < 4; mt++) {
                MMA16(acc[mt][2 * p],     aF[ks][mt], bF[nb][0], bF[nb][1]);
                MMA16(acc[mt][2 * p + 1], aF[ks][mt], bF[nb][2], bF[nb][3]);
            }
            if (grp == 6 && kt + 1 < KT) STS_TILE(buf ^ 1);
        }
        __syncthreads();
    }

    // ---- epilogue: add bias, store ----
    const float* bp = bias + (size_t)r * OUT_D + n0;
    #pragma unroll
    for (int mt = 0; mt < 4; mt++) {
        #pragma unroll
        for (int nt = 0; nt < 8; nt++) {
            int row0 = wm * 64 + mt * 16 + g;
            int col  = wn * 64 + nt * 8 + tg * 2;
            float b0 = bp[col];
            float b1 = bp[col + 1];
            float2 v0 = make_float2(acc[mt][nt][0] + b0, acc[mt][nt][1] + b1);
            float2 v1 = make_float2(acc[mt][nt][2] + b0, acc[mt][nt][3] + b1);
            size_t o0 = ((size_t)(m0 + row0)     * ROWG + r) * OUT_D + n0 + col;
            size_t o1 = ((size_t)(m0 + row0 + 8) * ROWG + r) * OUT_D + n0 + col;
            *reinterpret_cast<float2*>(out + o0) = v0;
            *reinterpret_cast<float2*>(out + o1) = v1;
        }
    }
}

extern "C" void kernel_launch(void* const* d_in, const int* in_sizes, int n_in,
                              void* d_out, int out_size) {
    const float* x    = (const float*)d_in[0];  // (512, 64, 1024)
    const float* W    = (const float*)d_in[1];  // (64, 1024, 1024)
    const float* bias = (const float*)d_in[2];  // (64, 1024)
    float* out = (float*)d_out;                 // (512, 64, 1024)

    cudaFuncSetAttribute(gmlp_f16pipe,
                         cudaFuncAttributeMaxDynamicSharedMemorySize, SMEM_TOTAL);
    dim3 grid(OUT_D / BN, BATCH / BM, ROWG);    // (4, 4, 64)
    gmlp_f16pipe<<<grid, 256, SMEM_TOTAL>>>(x, W, bias, out);
}

// round 11
// speedup vs baseline: 1.0453x; 1.0453x over previous
#include <cuda_runtime.h>
#include <cstdint>

// ---------------- problem constants ----------------
#define ROWG   64
#define IN_DIM 1024
#define OUT_D  1024
#define BATCH  512

// ---------------- tiling ----------------
#define BM 128
#define BN 256
#define BK 32
#define KT (IN_DIM / BK)   // 32 k-tiles

// ---------------- smem layout (bytes) ----------------
#define A_ROW_B 64                  // 32 fp16, no pad (XOR swizzle)
#define A_STG   (BM * A_ROW_B)      // 8192
#define B_ROW_B 528                 // 256 fp16 (512B) + 16B pad
#define B_STG   (BK * B_ROW_B)      // 16896
#define STAGES  3
#define SMEM_TOTAL (STAGES * (A_STG + B_STG))  // 75264

__device__ __forceinline__ uint32_t packh(float hi, float lo) {
    uint32_t w;
    asm("cvt.rn.f16x2.f32 %0, %1, %2;" : "=r"(w) : "f"(hi), "f"(lo));
    return w;
}

#define LDSM4(R, ADDR) \
    asm volatile("ldmatrix.sync.aligned.m8n8.x4.shared.b16 {%0,%1,%2,%3}, [%4];" \
        : "=r"((R)[0]), "=r"((R)[1]), "=r"((R)[2]), "=r"((R)[3]) : "r"(ADDR))

#define LDSM4T(R, ADDR) \
    asm volatile("ldmatrix.sync.aligned.m8n8.x4.trans.shared.b16 {%0,%1,%2,%3}, [%4];" \
        : "=r"((R)[0]), "=r"((R)[1]), "=r"((R)[2]), "=r"((R)[3]) : "r"(ADDR))

#define MMA16(C, A, B0, B1) \
    asm volatile("mma.sync.aligned.m16n8k16.row.col.f32.f16.f16.f32 " \
        "{%0,%1,%2,%3}, {%4,%5,%6,%7}, {%8,%9}, {%0,%1,%2,%3};" \
        : "+f"((C)[0]), "+f"((C)[1]), "+f"((C)[2]), "+f"((C)[3]) \
        : "r"((A)[0]), "r"((A)[1]), "r"((A)[2]), "r"((A)[3]), "r"(B0), "r"(B1))

__global__ __launch_bounds__(256, 1)
void gmlp_f16s3(const float* __restrict__ x,
                const float* __restrict__ W,
                const float* __restrict__ bias,
                float* __restrict__ out)
{
    extern __shared__ __align__(16) char smem[];
    const uint32_t sbA = (uint32_t)__cvta_generic_to_shared(smem);
    const uint32_t sbB = sbA + STAGES * A_STG;

    const int r  = blockIdx.z;
    const int n0 = blockIdx.x * BN;
    const int m0 = blockIdx.y * BM;

    const int tid  = threadIdx.x;
    const int wid  = tid >> 5;
    const int lane = tid & 31;
    const int wm   = wid & 1;            // 2 m-warps of 64 rows
    const int wn   = wid >> 1;           // 4 n-warps of 64 cols
    const int g    = lane >> 2;
    const int tg   = lane & 3;

    // ---- loader: A (128 rows x 32 fp32), fully coalesced ----
    const int arow = tid >> 2;
    const int ak   = (tid & 3) * 8;
    const float* xA = x + (size_t)(m0 + arow) * (ROWG * IN_DIM)
                        + (size_t)r * IN_DIM + ak;
    const size_t A_C1 = (size_t)64 * (ROWG * IN_DIM);
    const uint32_t saA = sbA + arow * A_ROW_B
                       + (((tid & 3) ^ ((tid >> 3) & 3)) * 16);

    // ---- loader: B (32 k-rows x 256 fp32), fully coalesced ----
    const int brow = tid >> 3;
    const float* xB = W + (size_t)r * IN_DIM * OUT_D
                        + (size_t)brow * OUT_D + n0 + (tid & 7) * 8;
    const uint32_t saB = sbB + brow * B_ROW_B + (tid & 7) * 16;

    // ---- consumer ldmatrix base addresses ----
    const int v = ((lane & 15) >> 1) & 3;
    const int h = lane >> 4;
    const uint32_t aBase = sbA + (wm * 64 + (lane & 15)) * A_ROW_B + ((h ^ v) * 16);
    const uint32_t bBase = sbB + ((lane & 7) + ((lane >> 3) & 1) * 8) * B_ROW_B
                               + (wn * 8 + h) * 16;

    float acc[4][8][4];
    #pragma unroll
    for (int mt = 0; mt < 4; mt++)
        #pragma unroll
        for (int nt = 0; nt < 8; nt++)
            #pragma unroll
            for (int i = 0; i < 4; i++)
                acc[mt][nt][i] = 0.0f;

    float stA[16], stB[32];

#define LOAD_GLB(T) do {                                                     \
    const float4* a0_ = (const float4*)(xA + (size_t)(T) * BK);              \
    const float4* a1_ = (const float4*)(xA + (size_t)(T) * BK + A_C1);       \
    float4 v_;                                                               \
    v_ = a0_[0]; stA[0]=v_.x; stA[1]=v_.y; stA[2]=v_.z; stA[3]=v_.w;         \
    v_ = a0_[1]; stA[4]=v_.x; stA[5]=v_.y; stA[6]=v_.z; stA[7]=v_.w;         \
    v_ = a1_[0]; stA[8]=v_.x; stA[9]=v_.y; stA[10]=v_.z; stA[11]=v_.w;       \
    v_ = a1_[1]; stA[12]=v_.x; stA[13]=v_.y; stA[14]=v_.z; stA[15]=v_.w;     \
    _Pragma("unroll")                                                        \
    for (int c_ = 0; c_ < 4; c_++) {                                         \
        const float4* b_ = (const float4*)(xB + (size_t)(T) * BK * OUT_D + c_ * 64); \
        float4 u0_ = b_[0], u1_ = b_[1];                                     \
        stB[c_*8+0]=u0_.x; stB[c_*8+1]=u0_.y; stB[c_*8+2]=u0_.z; stB[c_*8+3]=u0_.w; \
        stB[c_*8+4]=u1_.x; stB[c_*8+5]=u1_.y; stB[c_*8+6]=u1_.z; stB[c_*8+7]=u1_.w; \
    }                                                                        \
} while (0)

#define STS_TILE(BUF) do {                                                   \
    asm volatile("st.shared.v4.b32 [%0], {%1,%2,%3,%4};"                     \
        :: "r"(saA + (BUF) * A_STG),                                         \
           "r"(packh(stA[1],stA[0])), "r"(packh(stA[3],stA[2])),             \
           "r"(packh(stA[5],stA[4])), "r"(packh(stA[7],stA[6])));            \
    asm volatile("st.shared.v4.b32 [%0], {%1,%2,%3,%4};"                     \
        :: "r"(saA + (BUF) * A_STG + 64 * A_ROW_B),                          \
           "r"(packh(stA[9],stA[8])), "r"(packh(stA[11],stA[10])),           \
           "r"(packh(stA[13],stA[12])), "r"(packh(stA[15],stA[14])));        \
    _Pragma("unroll")                                                        \
    for (int c_ = 0; c_ < 4; c_++) {                                         \
        asm volatile("st.shared.v4.b32 [%0], {%1,%2,%3,%4};"                 \
            :: "r"(saB + (BUF) * B_STG + c_ * 128),                          \
               "r"(packh(stB[c_*8+1],stB[c_*8+0])), "r"(packh(stB[c_*8+3],stB[c_*8+2])), \
               "r"(packh(stB[c_*8+5],stB[c_*8+4])), "r"(packh(stB[c_*8+7],stB[c_*8+6]))); \
    }                                                                        \
} while (0)

#define COMPUTE(BUF) do {                                                    \
    _Pragma("unroll")                                                        \
    for (int ks_ = 0; ks_ < 2; ks_++) {                                      \
        uint32_t a_[4][4];                                                   \
        _Pragma("unroll")                                                    \
        for (int mt_ = 0; mt_ < 4; mt_++)                                    \
            LDSM4(a_[mt_], (aBase + (BUF) * A_STG + mt_ * (16 * A_ROW_B)) ^ (ks_ * 32)); \
        _Pragma("unroll")                                                    \
        for (int p_ = 0; p_ < 4; p_++) {                                     \
            uint32_t bb_[4];                                                 \
            LDSM4T(bb_, bBase + (BUF) * B_STG + ks_ * (16 * B_ROW_B) + p_ * 32); \
            _Pragma("unroll")                                                \
            for (int mt_ = 0; mt_ < 4; mt_++) {                              \
                MMA16(acc[mt_][2 * p_],     a_[mt_], bb_[0], bb_[1]);        \
                MMA16(acc[mt_][2 * p_ + 1], a_[mt_], bb_[2], bb_[3]);        \
            }                                                                \
        }                                                                    \
    }                                                                        \
} while (0)

    // ---- prologue: tile0 -> smem, tile1 -> staging regs ----
    LOAD_GLB(0);
    STS_TILE(0);
    LOAD_GLB(1);
    __syncthreads();

    // ---- main loop: 3-stage ring, STS before LOAD (full-tile LDG slack) ----
    int s_sts = 1;   // stage receiving tile kt+1
    #pragma unroll 1
    for (int kt = 0; kt < KT; kt++) {
        const int s_cmp = (s_sts + 2) % STAGES;   // stage kt%3
        if (kt + 1 < KT) STS_TILE(s_sts);          // regs loaded at iter kt-1
        if (kt + 2 < KT) LOAD_GLB(kt + 2);         // refill staging regs
        COMPUTE(s_cmp);
        __syncthreads();
        if (++s_sts == STAGES) s_sts = 0;
    }

    // ---- epilogue: add bias, store ----
    const float* bp = bias + (size_t)r * OUT_D + n0;
    #pragma unroll
    for (int mt = 0; mt < 4; mt++) {
        #pragma unroll
        for (int nt = 0; nt < 8; nt++) {
            int row0 = wm * 64 + mt * 16 + g;
            int col  = wn * 64 + nt * 8 + tg * 2;
            float b0 = bp[col];
            float b1 = bp[col + 1];
            float2 v0 = make_float2(acc[mt][nt][0] + b0, acc[mt][nt][1] + b1);
            float2 v1 = make_float2(acc[mt][nt][2] + b0, acc[mt][nt][3] + b1);
            size_t o0 = ((size_t)(m0 + row0)     * ROWG + r) * OUT_D + n0 + col;
            size_t o1 = ((size_t)(m0 + row0 + 8) * ROWG + r) * OUT_D + n0 + col;
            *reinterpret_cast<float2*>(out + o0) = v0;
            *reinterpret_cast<float2*>(out + o1) = v1;
        }
    }
}

extern "C" void kernel_launch(void* const* d_in, const int* in_sizes, int n_in,
                              void* d_out, int out_size) {
    const float* x    = (const float*)d_in[0];  // (512, 64, 1024)
    const float* W    = (const float*)d_in[1];  // (64, 1024, 1024)
    const float* bias = (const float*)d_in[2];  // (64, 1024)
    float* out = (float*)d_out;                 // (512, 64, 1024)

    cudaFuncSetAttribute(gmlp_f16s3,
                         cudaFuncAttributeMaxDynamicSharedMemorySize, SMEM_TOTAL);
    dim3 grid(OUT_D / BN, BATCH / BM, ROWG);    // (4, 4, 64)
    gmlp_f16s3<<<grid, 256, SMEM_TOTAL>>>(x, W, bias, out);
}